// round 8
// baseline (speedup 1.0000x reference)
#include <cuda_runtime.h>
#include <cuda_bf16.h>
#include <math.h>
#include <stdint.h>

// Problem constants
#define EMBED 128
#define HHID  512
#define MAXN  50000
#define MAXM  50000
#define MAXE  400000

// ---------------------------------------------------------------------------
// Scratch
// ---------------------------------------------------------------------------
__device__ __align__(16) float g_hs[MAXN * HHID];
__device__ __align__(16) float g_ht[MAXM * HHID];
__device__ __align__(16) float g_ms[MAXN * EMBED];
__device__ __align__(16) float g_agg[MAXM * EMBED];
__device__ int g_counts[MAXM];
__device__ int g_cursor[MAXM];
__device__ int g_offsets[MAXM + 1];
__device__ int g_sorted_src[MAXE];
// per 128-col block: BT_hi[128n][128k] then BT_lo[128n][128k], plain row-major bf16
__device__ __align__(16) __nv_bfloat16 g_wimg_s[4 * 32768];
__device__ __align__(16) __nv_bfloat16 g_wimg_t[4 * 32768];
__device__ __align__(16) __nv_bfloat16 g_wimg_m[32768];
__device__ __align__(16) __nv_bfloat16 g_wimg_o[32768];

// ---------------------------------------------------------------------------
// helpers
// ---------------------------------------------------------------------------
__device__ __forceinline__ uint32_t smem_u32(const void* p) {
    uint32_t a;
    asm("{ .reg .u64 t; cvta.to.shared.u64 t, %1; cvt.u32.u64 %0, t; }" : "=r"(a) : "l"(p));
    return a;
}

__device__ __forceinline__ void ldsm_x4(uint32_t& r0, uint32_t& r1, uint32_t& r2, uint32_t& r3,
                                        uint32_t addr) {
    asm volatile("ldmatrix.sync.aligned.m8n8.x4.shared.b16 {%0,%1,%2,%3}, [%4];"
                 : "=r"(r0), "=r"(r1), "=r"(r2), "=r"(r3) : "r"(addr));
}

__device__ __forceinline__ void mma_bf16(float* d, const uint32_t* a, uint32_t b0, uint32_t b1) {
    asm volatile("mma.sync.aligned.m16n8k16.row.col.f32.bf16.bf16.f32 "
                 "{%0,%1,%2,%3}, {%4,%5,%6,%7}, {%8,%9}, {%0,%1,%2,%3};"
                 : "+f"(d[0]), "+f"(d[1]), "+f"(d[2]), "+f"(d[3])
                 : "r"(a[0]), "r"(a[1]), "r"(a[2]), "r"(a[3]), "r"(b0), "r"(b1));
}

// Branchless exact-GELU: erf via Abramowitz-Stegun 7.1.26 (|err| <= 1.5e-7)
__device__ __forceinline__ float gelu_fast(float x) {
    float z  = 0.70710678118654752440f * x;
    float az = fabsf(z);
    float t  = __fdividef(1.0f, fmaf(0.3275911f, az, 1.0f));
    float w  = fmaf(1.061405429f, t, -1.453152027f);
    w = fmaf(w, t, 1.421413741f);
    w = fmaf(w, t, -0.284496736f);
    w = fmaf(w, t, 0.254829592f);
    w = w * t;
    float e = __expf(-az * az);
    float erf_az = fmaf(-w, e, 1.0f);
    float erf_z  = copysignf(erf_az, z);
    return 0.5f * x * (1.0f + erf_z);
}

// ---------------------------------------------------------------------------
// weight conversion -> BT (n-major) hi/lo bf16 images
// ---------------------------------------------------------------------------
__global__ void wconv_kernel(const float* __restrict__ W, __nv_bfloat16* __restrict__ img, int ncols) {
    int i = blockIdx.x * 256 + threadIdx.x;
    int total = 128 * ncols;
    if (i >= total) return;
    int k = i / ncols, c = i - k * ncols;
    int nb = c >> 7, n = c & 127;
    float x = W[i];
    __nv_bfloat16 h = __float2bfloat16(x);
    __nv_bfloat16 l = __float2bfloat16(x - __bfloat162float(h));
    __nv_bfloat16* base = img + (size_t)nb * 32768;
    base[n * 128 + k] = h;
    base[16384 + n * 128 + k] = l;
}

// ---------------------------------------------------------------------------
// HMMA GEMM: C[rows, ncols] = A[rows,128] @ B[128,ncols] + bias
// bf16x3 split (hi*hi + hi*lo + lo*hi), fp32 accumulate.
// CTA: 128x128 tile, 256 threads (8 warps), warp tile 32x64.
// ---------------------------------------------------------------------------
#define SMS 136                       // smem row stride in bf16 (272 B)
#define SM_TILE (128 * SMS)           // elements per tile image
#define TCG_SMEM_BYTES (4 * SM_TILE * 2)

__global__ void __launch_bounds__(256, 1)
tc_gemm_kernel(const float* __restrict__ A, const __nv_bfloat16* __restrict__ Bimg,
               const float* __restrict__ bias, float* __restrict__ C,
               int rows, int ncols) {
    extern __shared__ __align__(16) __nv_bfloat16 sm[];
    __nv_bfloat16* sAh = sm;
    __nv_bfloat16* sAl = sm + SM_TILE;
    __nv_bfloat16* sBh = sm + 2 * SM_TILE;
    __nv_bfloat16* sBl = sm + 3 * SM_TILE;

    int tid = threadIdx.x, wid = tid >> 5, lane = tid & 31;
    int row0 = blockIdx.x * 128, col0 = blockIdx.y * 128;

    // ---- load B tile (pre-converted BT hi/lo), pad stride ----
    {
        const uint4* src = (const uint4*)(Bimg + (size_t)blockIdx.y * 32768);
        for (int idx = tid; idx < 2048; idx += 256) {
            int n = idx >> 4, k8 = (idx & 15);
            uint4 vh = src[idx];
            uint4 vl = src[2048 + idx];
            *(uint4*)(sBh + n * SMS + k8 * 8) = vh;
            *(uint4*)(sBl + n * SMS + k8 * 8) = vl;
        }
    }
    // ---- load + split-convert A tile ----
    for (int idx = tid; idx < 4096; idx += 256) {
        int r = idx >> 5, k0 = (idx & 31) * 4;
        float4 v = make_float4(0.f, 0.f, 0.f, 0.f);
        int gr = row0 + r;
        if (gr < rows) v = *(const float4*)(A + (size_t)gr * 128 + k0);
        uint32_t h01, h23;
        asm("cvt.rn.satfinite.bf16x2.f32 %0, %1, %2;" : "=r"(h01) : "f"(v.y), "f"(v.x));
        asm("cvt.rn.satfinite.bf16x2.f32 %0, %1, %2;" : "=r"(h23) : "f"(v.w), "f"(v.z));
        float r0f = v.x - __uint_as_float(h01 << 16);
        float r1f = v.y - __uint_as_float(h01 & 0xffff0000u);
        float r2f = v.z - __uint_as_float(h23 << 16);
        float r3f = v.w - __uint_as_float(h23 & 0xffff0000u);
        uint32_t l01, l23;
        asm("cvt.rn.satfinite.bf16x2.f32 %0, %1, %2;" : "=r"(l01) : "f"(r1f), "f"(r0f));
        asm("cvt.rn.satfinite.bf16x2.f32 %0, %1, %2;" : "=r"(l23) : "f"(r3f), "f"(r2f));
        *(uint2*)(sAh + r * SMS + k0) = make_uint2(h01, h23);
        *(uint2*)(sAl + r * SMS + k0) = make_uint2(l01, l23);
    }
    __syncthreads();

    int wm = (wid & 3) * 32;
    int wn = (wid >> 2) * 64;

    float acc[2][8][4];
    #pragma unroll
    for (int i = 0; i < 2; i++)
        #pragma unroll
        for (int j = 0; j < 8; j++)
            #pragma unroll
            for (int q = 0; q < 4; q++) acc[i][j][q] = 0.f;

    uint32_t a_base_h = smem_u32(sAh) + (((wm + (lane & 15)) * SMS + ((lane >> 4) << 3)) << 1);
    uint32_t a_base_l = a_base_h + (uint32_t)(SM_TILE << 1);
    uint32_t b_row = (uint32_t)(wn + ((lane & 16) >> 1) + (lane & 7));
    uint32_t b_base_h = smem_u32(sBh) + ((b_row * SMS + (lane & 8)) << 1);
    uint32_t b_base_l = b_base_h + (uint32_t)(SM_TILE << 1);

    #pragma unroll
    for (int ks = 0; ks < 8; ks++) {
        uint32_t koff = (uint32_t)(ks * 16 * 2);
        uint32_t ah[2][4], al[2][4];
        #pragma unroll
        for (int mt = 0; mt < 2; mt++) {
            uint32_t off = koff + (uint32_t)((mt * 16 * SMS) << 1);
            ldsm_x4(ah[mt][0], ah[mt][1], ah[mt][2], ah[mt][3], a_base_h + off);
            ldsm_x4(al[mt][0], al[mt][1], al[mt][2], al[mt][3], a_base_l + off);
        }
        #pragma unroll
        for (int np = 0; np < 4; np++) {
            uint32_t off = koff + (uint32_t)((np * 16 * SMS) << 1);
            uint32_t bh[4], bl[4];
            ldsm_x4(bh[0], bh[1], bh[2], bh[3], b_base_h + off);
            ldsm_x4(bl[0], bl[1], bl[2], bl[3], b_base_l + off);
            #pragma unroll
            for (int mt = 0; mt < 2; mt++) {
                mma_bf16(acc[mt][np * 2 + 0], ah[mt], bh[0], bh[1]);
                mma_bf16(acc[mt][np * 2 + 1], ah[mt], bh[2], bh[3]);
                mma_bf16(acc[mt][np * 2 + 0], ah[mt], bl[0], bl[1]);
                mma_bf16(acc[mt][np * 2 + 1], ah[mt], bl[2], bl[3]);
                mma_bf16(acc[mt][np * 2 + 0], al[mt], bh[0], bh[1]);
                mma_bf16(acc[mt][np * 2 + 1], al[mt], bh[2], bh[3]);
            }
        }
    }

    int g = lane >> 2, tg = lane & 3;
    #pragma unroll
    for (int mt = 0; mt < 2; mt++) {
        int r_lo = row0 + wm + mt * 16 + g;
        int r_hi = r_lo + 8;
        #pragma unroll
        for (int nt = 0; nt < 8; nt++) {
            int gc = col0 + wn + nt * 8 + tg * 2;
            float b0 = bias[gc], b1 = bias[gc + 1];
            if (r_lo < rows) {
                float2 o = make_float2(acc[mt][nt][0] + b0, acc[mt][nt][1] + b1);
                *(float2*)(C + (size_t)r_lo * ncols + gc) = o;
            }
            if (r_hi < rows) {
                float2 o = make_float2(acc[mt][nt][2] + b0, acc[mt][nt][3] + b1);
                *(float2*)(C + (size_t)r_hi * ncols + gc) = o;
            }
        }
    }
}

// ---------------------------------------------------------------------------
// CSR build
// ---------------------------------------------------------------------------
__global__ void zero2_kernel(int* a, int* b, int n) {
    int i = blockIdx.x * blockDim.x + threadIdx.x;
    if (i < n) { a[i] = 0; b[i] = 0; }
}
__global__ void hist_kernel(const int* __restrict__ etgt, int* __restrict__ counts, int E) {
    int i = blockIdx.x * blockDim.x + threadIdx.x;
    if (i < E) atomicAdd(&counts[etgt[i]], 1);
}
__global__ void scan_kernel(const int* __restrict__ counts, int* __restrict__ offsets, int M) {
    __shared__ int wsum[32];
    int t = threadIdx.x;
    int chunk = (M + 1023) >> 10;
    int b0 = t * chunk, b1 = b0 + chunk;
    if (b0 > M) b0 = M;
    if (b1 > M) b1 = M;
    int s = 0;
    for (int i = b0; i < b1; i++) s += counts[i];
    int lane = t & 31, w = t >> 5;
    int v = s;
    #pragma unroll
    for (int o = 1; o < 32; o <<= 1) { int x = __shfl_up_sync(0xffffffffu, v, o); if (lane >= o) v += x; }
    if (lane == 31) wsum[w] = v;
    __syncthreads();
    if (w == 0) {
        int x = wsum[lane];
        #pragma unroll
        for (int o = 1; o < 32; o <<= 1) { int y = __shfl_up_sync(0xffffffffu, x, o); if (lane >= o) x += y; }
        wsum[lane] = x;
    }
    __syncthreads();
    int run = v - s + (w > 0 ? wsum[w - 1] : 0);
    for (int i = b0; i < b1; i++) { offsets[i] = run; run += counts[i]; }
    if (t == 1023) offsets[M] = run;
}
__global__ void scatter_kernel(const int* __restrict__ etgt, const int* __restrict__ esrc,
                               const int* __restrict__ offsets, int* __restrict__ cursor,
                               int* __restrict__ ssrc, int E) {
    int i = blockIdx.x * blockDim.x + threadIdx.x;
    if (i < E) {
        int tg = etgt[i];
        int pos = offsets[tg] + atomicAdd(&cursor[tg], 1);
        ssrc[pos] = esrc[i];
    }
}

// ---------------------------------------------------------------------------
// Edge attention, SINGLE PASS with online softmax. One warp per target.
// Per edge: gather hs row (16 indep float4/lane-set) + msg (1 float4/lane),
// logits via warp butterfly, running (max, denom, weighted-acc) update.
// ---------------------------------------------------------------------------
__global__ void __launch_bounds__(256)
edge_attn_kernel(const int* __restrict__ sorted_src,
                 const int* __restrict__ offsets,
                 const float4* __restrict__ hs4,
                 const float4* __restrict__ ht4,
                 const float4* __restrict__ ms4,
                 const float4* __restrict__ aw4,
                 float4* __restrict__ agg4,
                 int M) {
    int warp = (blockIdx.x * blockDim.x + threadIdx.x) >> 5;
    int lane = threadIdx.x & 31;
    if (warp >= M) return;
    int tgt = warp;
    int beg = offsets[tgt], end = offsets[tgt + 1];

    float4 htv[4], aw[4];
    #pragma unroll
    for (int q = 0; q < 4; q++) {
        htv[q] = ht4[(size_t)tgt * 128 + lane + 32 * q];
        aw[q] = aw4[q * 32 + lane];
    }

    const float NEG = -3.4e38f;
    float m0 = NEG, m1 = NEG, m2 = NEG, m3 = NEG;
    float d0 = 0.f, d1 = 0.f, d2 = 0.f, d3 = 0.f;
    float4 acc = make_float4(0.f, 0.f, 0.f, 0.f);
    int h = lane >> 3;

    int s = (beg < end) ? sorted_src[beg] : 0;
    for (int p = beg; p < end; p++) {
        int snext = (p + 1 < end) ? sorted_src[p + 1] : s;
        // message load issued early, independent of the logit chain
        float4 msg = ms4[(size_t)s * 32 + lane];
        float part[4];
        #pragma unroll
        for (int q = 0; q < 4; q++) {
            float4 hv = hs4[(size_t)s * 128 + lane + 32 * q];
            float x0 = gelu_fast(hv.x + htv[q].x);
            float x1 = gelu_fast(hv.y + htv[q].y);
            float x2 = gelu_fast(hv.z + htv[q].z);
            float x3 = gelu_fast(hv.w + htv[q].w);
            part[q] = fmaf(x0, aw[q].x, fmaf(x1, aw[q].y, fmaf(x2, aw[q].z, x3 * aw[q].w)));
        }
        #pragma unroll
        for (int q = 0; q < 4; q++) {
            #pragma unroll
            for (int o = 16; o > 0; o >>= 1)
                part[q] += __shfl_xor_sync(0xffffffffu, part[q], o);
        }
        // online softmax update (all lanes compute all heads)
        float nm0 = fmaxf(m0, part[0]), nm1 = fmaxf(m1, part[1]);
        float nm2 = fmaxf(m2, part[2]), nm3 = fmaxf(m3, part[3]);
        float g0 = __expf(m0 - nm0), g1 = __expf(m1 - nm1);
        float g2 = __expf(m2 - nm2), g3 = __expf(m3 - nm3);
        float e0 = __expf(part[0] - nm0), e1 = __expf(part[1] - nm1);
        float e2 = __expf(part[2] - nm2), e3 = __expf(part[3] - nm3);
        d0 = fmaf(d0, g0, e0); d1 = fmaf(d1, g1, e1);
        d2 = fmaf(d2, g2, e2); d3 = fmaf(d3, g3, e3);
        m0 = nm0; m1 = nm1; m2 = nm2; m3 = nm3;
        float gh = (h < 2) ? ((h == 0) ? g0 : g1) : ((h == 2) ? g2 : g3);
        float eh = (h < 2) ? ((h == 0) ? e0 : e1) : ((h == 2) ? e2 : e3);
        acc.x = fmaf(acc.x, gh, msg.x * eh);
        acc.y = fmaf(acc.y, gh, msg.y * eh);
        acc.z = fmaf(acc.z, gh, msg.z * eh);
        acc.w = fmaf(acc.w, gh, msg.w * eh);
        s = snext;
    }

    float dh = (h < 2) ? ((h == 0) ? d0 : d1) : ((h == 2) ? d2 : d3);
    float inv = (end > beg) ? (1.0f / dh) : 0.0f;
    acc.x *= inv; acc.y *= inv; acc.z *= inv; acc.w *= inv;
    agg4[(size_t)tgt * 32 + lane] = acc;
}

// ---------------------------------------------------------------------------
// launch
// ---------------------------------------------------------------------------
extern "C" void kernel_launch(void* const* d_in, const int* in_sizes, int n_in,
                              void* d_out, int out_size) {
    const float* src_f = (const float*)d_in[0];
    const float* tgt_f = (const float*)d_in[1];
    const int*   etgt  = (const int*)d_in[2];
    const int*   esrc  = (const int*)d_in[3];
    const float* Ws    = (const float*)d_in[4];
    const float* bs    = (const float*)d_in[5];
    const float* Wt    = (const float*)d_in[6];
    const float* bt    = (const float*)d_in[7];
    const float* aw    = (const float*)d_in[8];
    const float* Wm    = (const float*)d_in[9];
    const float* bm    = (const float*)d_in[10];
    const float* Wo    = (const float*)d_in[11];
    const float* bo    = (const float*)d_in[12];
    float* out = (float*)d_out;

    int N = in_sizes[0] / EMBED;
    int M = in_sizes[1] / EMBED;
    int E = in_sizes[2];

    float *p_hs, *p_ht, *p_ms, *p_agg;
    int *p_counts, *p_cursor, *p_offsets, *p_ssrc;
    __nv_bfloat16 *p_ws, *p_wt, *p_wm, *p_wo;
    cudaGetSymbolAddress((void**)&p_hs, g_hs);
    cudaGetSymbolAddress((void**)&p_ht, g_ht);
    cudaGetSymbolAddress((void**)&p_ms, g_ms);
    cudaGetSymbolAddress((void**)&p_agg, g_agg);
    cudaGetSymbolAddress((void**)&p_counts, g_counts);
    cudaGetSymbolAddress((void**)&p_cursor, g_cursor);
    cudaGetSymbolAddress((void**)&p_offsets, g_offsets);
    cudaGetSymbolAddress((void**)&p_ssrc, g_sorted_src);
    cudaGetSymbolAddress((void**)&p_ws, g_wimg_s);
    cudaGetSymbolAddress((void**)&p_wt, g_wimg_t);
    cudaGetSymbolAddress((void**)&p_wm, g_wimg_m);
    cudaGetSymbolAddress((void**)&p_wo, g_wimg_o);

    cudaFuncSetAttribute(tc_gemm_kernel,
                         cudaFuncAttributeMaxDynamicSharedMemorySize, TCG_SMEM_BYTES);

    // launch order chosen so the 5th launch (ncu capture slot) is the big hs GEMM
    zero2_kernel<<<(M + 255) / 256, 256>>>(p_counts, p_cursor, M);                 // 1
    wconv_kernel<<<(128 * HHID + 255) / 256, 256>>>(Ws, p_ws, HHID);               // 2
    wconv_kernel<<<(128 * HHID + 255) / 256, 256>>>(Wt, p_wt, HHID);               // 3
    wconv_kernel<<<(128 * EMBED + 255) / 256, 256>>>(Wm, p_wm, EMBED);             // 4
    {
        dim3 g((N + 127) / 128, HHID / 128);                                       // 5 (captured)
        tc_gemm_kernel<<<g, 256, TCG_SMEM_BYTES>>>(src_f, p_ws, bs, p_hs, N, HHID);
    }
    {
        dim3 g((M + 127) / 128, HHID / 128);                                       // 6
        tc_gemm_kernel<<<g, 256, TCG_SMEM_BYTES>>>(tgt_f, p_wt, bt, p_ht, M, HHID);
    }
    {
        dim3 g((N + 127) / 128, 1);                                                // 7
        tc_gemm_kernel<<<g, 256, TCG_SMEM_BYTES>>>(src_f, p_wm, bm, p_ms, N, EMBED);
    }
    hist_kernel<<<(E + 255) / 256, 256>>>(etgt, p_counts, E);                      // 8
    scan_kernel<<<1, 1024>>>(p_counts, p_offsets, M);                              // 9
    scatter_kernel<<<(E + 255) / 256, 256>>>(etgt, esrc, p_offsets, p_cursor, p_ssrc, E); // 10
    {
        int blocks = (M + 7) / 8;                                                  // 11
        edge_attn_kernel<<<blocks, 256>>>(p_ssrc, p_offsets,
                                          (const float4*)p_hs, (const float4*)p_ht,
                                          (const float4*)p_ms, (const float4*)aw,
                                          (float4*)p_agg, M);
    }
    wconv_kernel<<<(128 * EMBED + 255) / 256, 256>>>(Wo, p_wo, EMBED);             // 12
    {
        dim3 g((M + 127) / 128, 1);                                                // 13
        tc_gemm_kernel<<<g, 256, TCG_SMEM_BYTES>>>(p_agg, p_wo, bo, out, M, EMBED);
    }
}

// round 9
// speedup vs baseline: 1.1673x; 1.1673x over previous
#include <cuda_runtime.h>
#include <cuda_bf16.h>
#include <math.h>
#include <stdint.h>

// Problem constants
#define EMBED 128
#define HHID  512
#define MAXN  50000
#define MAXM  50000
#define MAXE  400000

// ---------------------------------------------------------------------------
// Scratch
// ---------------------------------------------------------------------------
__device__ __align__(16) float g_hs[MAXN * HHID];
__device__ __align__(16) float g_ht[MAXM * HHID];
__device__ __align__(16) float g_ms[MAXN * EMBED];
__device__ __align__(16) float g_agg[MAXM * EMBED];
__device__ int g_counts[MAXM];
__device__ int g_cursor[MAXM];
__device__ int g_offsets[MAXM + 1];
__device__ int g_sorted_src[MAXE];
// per 128-col block: BT_hi[128n][128k] then BT_lo[128n][128k], plain row-major bf16
__device__ __align__(16) __nv_bfloat16 g_wimg_s[4 * 32768];
__device__ __align__(16) __nv_bfloat16 g_wimg_t[4 * 32768];
__device__ __align__(16) __nv_bfloat16 g_wimg_m[32768];
__device__ __align__(16) __nv_bfloat16 g_wimg_o[32768];

// ---------------------------------------------------------------------------
// helpers
// ---------------------------------------------------------------------------
__device__ __forceinline__ uint32_t smem_u32(const void* p) {
    uint32_t a;
    asm("{ .reg .u64 t; cvta.to.shared.u64 t, %1; cvt.u32.u64 %0, t; }" : "=r"(a) : "l"(p));
    return a;
}

__device__ __forceinline__ void ldsm_x4(uint32_t& r0, uint32_t& r1, uint32_t& r2, uint32_t& r3,
                                        uint32_t addr) {
    asm volatile("ldmatrix.sync.aligned.m8n8.x4.shared.b16 {%0,%1,%2,%3}, [%4];"
                 : "=r"(r0), "=r"(r1), "=r"(r2), "=r"(r3) : "r"(addr));
}

__device__ __forceinline__ void mma_bf16(float* d, const uint32_t* a, uint32_t b0, uint32_t b1) {
    asm volatile("mma.sync.aligned.m16n8k16.row.col.f32.bf16.bf16.f32 "
                 "{%0,%1,%2,%3}, {%4,%5,%6,%7}, {%8,%9}, {%0,%1,%2,%3};"
                 : "+f"(d[0]), "+f"(d[1]), "+f"(d[2]), "+f"(d[3])
                 : "r"(a[0]), "r"(a[1]), "r"(a[2]), "r"(a[3]), "r"(b0), "r"(b1));
}

// Branchless exact-GELU: erf via Abramowitz-Stegun 7.1.26 (|err| <= 1.5e-7)
__device__ __forceinline__ float gelu_fast(float x) {
    float z  = 0.70710678118654752440f * x;
    float az = fabsf(z);
    float t  = __fdividef(1.0f, fmaf(0.3275911f, az, 1.0f));
    float w  = fmaf(1.061405429f, t, -1.453152027f);
    w = fmaf(w, t, 1.421413741f);
    w = fmaf(w, t, -0.284496736f);
    w = fmaf(w, t, 0.254829592f);
    w = w * t;
    float e = __expf(-az * az);
    float erf_az = fmaf(-w, e, 1.0f);
    float erf_z  = copysignf(erf_az, z);
    return 0.5f * x * (1.0f + erf_z);
}

// ---------------------------------------------------------------------------
// weight conversion -> BT (n-major) hi/lo bf16 images
// ---------------------------------------------------------------------------
__global__ void wconv_kernel(const float* __restrict__ W, __nv_bfloat16* __restrict__ img, int ncols) {
    int i = blockIdx.x * 256 + threadIdx.x;
    int total = 128 * ncols;
    if (i >= total) return;
    int k = i / ncols, c = i - k * ncols;
    int nb = c >> 7, n = c & 127;
    float x = W[i];
    __nv_bfloat16 h = __float2bfloat16(x);
    __nv_bfloat16 l = __float2bfloat16(x - __bfloat162float(h));
    __nv_bfloat16* base = img + (size_t)nb * 32768;
    base[n * 128 + k] = h;
    base[16384 + n * 128 + k] = l;
}

// ---------------------------------------------------------------------------
// HMMA GEMM: C[rows, ncols] = A[rows,128] @ B[128,ncols] + bias
// bf16x3 split (hi*hi + hi*lo + lo*hi), fp32 accumulate.
// CTA: 128x128 tile, 256 threads (8 warps), warp tile 32x64.
// ---------------------------------------------------------------------------
#define SMS 136                       // smem row stride in bf16 (272 B)
#define SM_TILE (128 * SMS)           // elements per tile image
#define TCG_SMEM_BYTES (4 * SM_TILE * 2)

__global__ void __launch_bounds__(256, 1)
tc_gemm_kernel(const float* __restrict__ A, const __nv_bfloat16* __restrict__ Bimg,
               const float* __restrict__ bias, float* __restrict__ C,
               int rows, int ncols) {
    extern __shared__ __align__(16) __nv_bfloat16 sm[];
    __nv_bfloat16* sAh = sm;
    __nv_bfloat16* sAl = sm + SM_TILE;
    __nv_bfloat16* sBh = sm + 2 * SM_TILE;
    __nv_bfloat16* sBl = sm + 3 * SM_TILE;

    int tid = threadIdx.x, wid = tid >> 5, lane = tid & 31;
    int row0 = blockIdx.x * 128, col0 = blockIdx.y * 128;

    {
        const uint4* src = (const uint4*)(Bimg + (size_t)blockIdx.y * 32768);
        for (int idx = tid; idx < 2048; idx += 256) {
            int n = idx >> 4, k8 = (idx & 15);
            uint4 vh = src[idx];
            uint4 vl = src[2048 + idx];
            *(uint4*)(sBh + n * SMS + k8 * 8) = vh;
            *(uint4*)(sBl + n * SMS + k8 * 8) = vl;
        }
    }
    for (int idx = tid; idx < 4096; idx += 256) {
        int r = idx >> 5, k0 = (idx & 31) * 4;
        float4 v = make_float4(0.f, 0.f, 0.f, 0.f);
        int gr = row0 + r;
        if (gr < rows) v = *(const float4*)(A + (size_t)gr * 128 + k0);
        uint32_t h01, h23;
        asm("cvt.rn.satfinite.bf16x2.f32 %0, %1, %2;" : "=r"(h01) : "f"(v.y), "f"(v.x));
        asm("cvt.rn.satfinite.bf16x2.f32 %0, %1, %2;" : "=r"(h23) : "f"(v.w), "f"(v.z));
        float r0f = v.x - __uint_as_float(h01 << 16);
        float r1f = v.y - __uint_as_float(h01 & 0xffff0000u);
        float r2f = v.z - __uint_as_float(h23 << 16);
        float r3f = v.w - __uint_as_float(h23 & 0xffff0000u);
        uint32_t l01, l23;
        asm("cvt.rn.satfinite.bf16x2.f32 %0, %1, %2;" : "=r"(l01) : "f"(r1f), "f"(r0f));
        asm("cvt.rn.satfinite.bf16x2.f32 %0, %1, %2;" : "=r"(l23) : "f"(r3f), "f"(r2f));
        *(uint2*)(sAh + r * SMS + k0) = make_uint2(h01, h23);
        *(uint2*)(sAl + r * SMS + k0) = make_uint2(l01, l23);
    }
    __syncthreads();

    int wm = (wid & 3) * 32;
    int wn = (wid >> 2) * 64;

    float acc[2][8][4];
    #pragma unroll
    for (int i = 0; i < 2; i++)
        #pragma unroll
        for (int j = 0; j < 8; j++)
            #pragma unroll
            for (int q = 0; q < 4; q++) acc[i][j][q] = 0.f;

    uint32_t a_base_h = smem_u32(sAh) + (((wm + (lane & 15)) * SMS + ((lane >> 4) << 3)) << 1);
    uint32_t a_base_l = a_base_h + (uint32_t)(SM_TILE << 1);
    uint32_t b_row = (uint32_t)(wn + ((lane & 16) >> 1) + (lane & 7));
    uint32_t b_base_h = smem_u32(sBh) + ((b_row * SMS + (lane & 8)) << 1);
    uint32_t b_base_l = b_base_h + (uint32_t)(SM_TILE << 1);

    #pragma unroll
    for (int ks = 0; ks < 8; ks++) {
        uint32_t koff = (uint32_t)(ks * 16 * 2);
        uint32_t ah[2][4], al[2][4];
        #pragma unroll
        for (int mt = 0; mt < 2; mt++) {
            uint32_t off = koff + (uint32_t)((mt * 16 * SMS) << 1);
            ldsm_x4(ah[mt][0], ah[mt][1], ah[mt][2], ah[mt][3], a_base_h + off);
            ldsm_x4(al[mt][0], al[mt][1], al[mt][2], al[mt][3], a_base_l + off);
        }
        #pragma unroll
        for (int np = 0; np < 4; np++) {
            uint32_t off = koff + (uint32_t)((np * 16 * SMS) << 1);
            uint32_t bh[4], bl[4];
            ldsm_x4(bh[0], bh[1], bh[2], bh[3], b_base_h + off);
            ldsm_x4(bl[0], bl[1], bl[2], bl[3], b_base_l + off);
            #pragma unroll
            for (int mt = 0; mt < 2; mt++) {
                mma_bf16(acc[mt][np * 2 + 0], ah[mt], bh[0], bh[1]);
                mma_bf16(acc[mt][np * 2 + 1], ah[mt], bh[2], bh[3]);
                mma_bf16(acc[mt][np * 2 + 0], ah[mt], bl[0], bl[1]);
                mma_bf16(acc[mt][np * 2 + 1], ah[mt], bl[2], bl[3]);
                mma_bf16(acc[mt][np * 2 + 0], al[mt], bh[0], bh[1]);
                mma_bf16(acc[mt][np * 2 + 1], al[mt], bh[2], bh[3]);
            }
        }
    }

    int g = lane >> 2, tg = lane & 3;
    #pragma unroll
    for (int mt = 0; mt < 2; mt++) {
        int r_lo = row0 + wm + mt * 16 + g;
        int r_hi = r_lo + 8;
        #pragma unroll
        for (int nt = 0; nt < 8; nt++) {
            int gc = col0 + wn + nt * 8 + tg * 2;
            float b0 = bias[gc], b1 = bias[gc + 1];
            if (r_lo < rows) {
                float2 o = make_float2(acc[mt][nt][0] + b0, acc[mt][nt][1] + b1);
                *(float2*)(C + (size_t)r_lo * ncols + gc) = o;
            }
            if (r_hi < rows) {
                float2 o = make_float2(acc[mt][nt][2] + b0, acc[mt][nt][3] + b1);
                *(float2*)(C + (size_t)r_hi * ncols + gc) = o;
            }
        }
    }
}

// ---------------------------------------------------------------------------
// CSR build
// ---------------------------------------------------------------------------
__global__ void zero2_kernel(int* a, int* b, int n) {
    int i = blockIdx.x * blockDim.x + threadIdx.x;
    if (i < n) { a[i] = 0; b[i] = 0; }
}
__global__ void hist_kernel(const int* __restrict__ etgt, int* __restrict__ counts, int E) {
    int i = blockIdx.x * blockDim.x + threadIdx.x;
    if (i < E) atomicAdd(&counts[etgt[i]], 1);
}
__global__ void scan_kernel(const int* __restrict__ counts, int* __restrict__ offsets, int M) {
    __shared__ int wsum[32];
    int t = threadIdx.x;
    int chunk = (M + 1023) >> 10;
    int b0 = t * chunk, b1 = b0 + chunk;
    if (b0 > M) b0 = M;
    if (b1 > M) b1 = M;
    int s = 0;
    for (int i = b0; i < b1; i++) s += counts[i];
    int lane = t & 31, w = t >> 5;
    int v = s;
    #pragma unroll
    for (int o = 1; o < 32; o <<= 1) { int x = __shfl_up_sync(0xffffffffu, v, o); if (lane >= o) v += x; }
    if (lane == 31) wsum[w] = v;
    __syncthreads();
    if (w == 0) {
        int x = wsum[lane];
        #pragma unroll
        for (int o = 1; o < 32; o <<= 1) { int y = __shfl_up_sync(0xffffffffu, x, o); if (lane >= o) x += y; }
        wsum[lane] = x;
    }
    __syncthreads();
    int run = v - s + (w > 0 ? wsum[w - 1] : 0);
    for (int i = b0; i < b1; i++) { offsets[i] = run; run += counts[i]; }
    if (t == 1023) offsets[M] = run;
}
__global__ void scatter_kernel(const int* __restrict__ etgt, const int* __restrict__ esrc,
                               const int* __restrict__ offsets, int* __restrict__ cursor,
                               int* __restrict__ ssrc, int E) {
    int i = blockIdx.x * blockDim.x + threadIdx.x;
    if (i < E) {
        int tg = etgt[i];
        int pos = offsets[tg] + atomicAdd(&cursor[tg], 1);
        ssrc[pos] = esrc[i];
    }
}

// ---------------------------------------------------------------------------
// Edge attention, HEAD-SPLIT: one warp per (target, head).
// Heads are independent end-to-end (softmax + 32 output dims per head),
// so no cross-warp merge. ~35 regs/thread -> high occupancy; short per-edge
// dependency chain (1 float4 gather, 4 gelus, one 5-shuffle butterfly,
// single-head online-softmax update).
// ---------------------------------------------------------------------------
__global__ void __launch_bounds__(256)
edge_attn_kernel(const int* __restrict__ sorted_src,
                 const int* __restrict__ offsets,
                 const float4* __restrict__ hs4,
                 const float4* __restrict__ ht4,
                 const float* __restrict__ ms,
                 const float4* __restrict__ aw4,
                 float* __restrict__ agg,
                 int M) {
    int gw = (blockIdx.x * blockDim.x + threadIdx.x) >> 5;  // global warp id
    int lane = threadIdx.x & 31;
    int tgt = gw >> 2;
    int h = gw & 3;
    if (tgt >= M) return;
    int beg = offsets[tgt], end = offsets[tgt + 1];

    int fidx = h * 32 + lane;                 // float4 index within 128-float4 row
    float4 htv = ht4[(size_t)tgt * 128 + fidx];
    float4 aw = aw4[fidx];

    float m = -3.4e38f;
    float d = 0.f;
    float acc = 0.f;
    int mdim = h * 32 + lane;                 // scalar msg dim for this lane

    int s = (beg < end) ? sorted_src[beg] : 0;
    for (int p = beg; p < end; p++) {
        int snext = (p + 1 < end) ? sorted_src[p + 1] : s;
        float msg = ms[(size_t)s * 128 + mdim];
        float4 hv = hs4[(size_t)s * 128 + fidx];
        float x0 = gelu_fast(hv.x + htv.x);
        float x1 = gelu_fast(hv.y + htv.y);
        float x2 = gelu_fast(hv.z + htv.z);
        float x3 = gelu_fast(hv.w + htv.w);
        float part = fmaf(x0, aw.x, fmaf(x1, aw.y, fmaf(x2, aw.z, x3 * aw.w)));
        #pragma unroll
        for (int o = 16; o > 0; o >>= 1)
            part += __shfl_xor_sync(0xffffffffu, part, o);
        // single-head online softmax
        float nm = fmaxf(m, part);
        float gm = __expf(m - nm);
        float e  = __expf(part - nm);
        d = fmaf(d, gm, e);
        acc = fmaf(acc, gm, msg * e);
        m = nm;
        s = snext;
    }

    float inv = (end > beg) ? (1.0f / d) : 0.0f;
    agg[(size_t)tgt * 128 + mdim] = acc * inv;
}

// ---------------------------------------------------------------------------
// launch
// ---------------------------------------------------------------------------
extern "C" void kernel_launch(void* const* d_in, const int* in_sizes, int n_in,
                              void* d_out, int out_size) {
    const float* src_f = (const float*)d_in[0];
    const float* tgt_f = (const float*)d_in[1];
    const int*   etgt  = (const int*)d_in[2];
    const int*   esrc  = (const int*)d_in[3];
    const float* Ws    = (const float*)d_in[4];
    const float* bs    = (const float*)d_in[5];
    const float* Wt    = (const float*)d_in[6];
    const float* bt    = (const float*)d_in[7];
    const float* aw    = (const float*)d_in[8];
    const float* Wm    = (const float*)d_in[9];
    const float* bm    = (const float*)d_in[10];
    const float* Wo    = (const float*)d_in[11];
    const float* bo    = (const float*)d_in[12];
    float* out = (float*)d_out;

    int N = in_sizes[0] / EMBED;
    int M = in_sizes[1] / EMBED;
    int E = in_sizes[2];

    float *p_hs, *p_ht, *p_ms, *p_agg;
    int *p_counts, *p_cursor, *p_offsets, *p_ssrc;
    __nv_bfloat16 *p_ws, *p_wt, *p_wm, *p_wo;
    cudaGetSymbolAddress((void**)&p_hs, g_hs);
    cudaGetSymbolAddress((void**)&p_ht, g_ht);
    cudaGetSymbolAddress((void**)&p_ms, g_ms);
    cudaGetSymbolAddress((void**)&p_agg, g_agg);
    cudaGetSymbolAddress((void**)&p_counts, g_counts);
    cudaGetSymbolAddress((void**)&p_cursor, g_cursor);
    cudaGetSymbolAddress((void**)&p_offsets, g_offsets);
    cudaGetSymbolAddress((void**)&p_ssrc, g_sorted_src);
    cudaGetSymbolAddress((void**)&p_ws, g_wimg_s);
    cudaGetSymbolAddress((void**)&p_wt, g_wimg_t);
    cudaGetSymbolAddress((void**)&p_wm, g_wimg_m);
    cudaGetSymbolAddress((void**)&p_wo, g_wimg_o);

    cudaFuncSetAttribute(tc_gemm_kernel,
                         cudaFuncAttributeMaxDynamicSharedMemorySize, TCG_SMEM_BYTES);

    zero2_kernel<<<(M + 255) / 256, 256>>>(p_counts, p_cursor, M);
    wconv_kernel<<<(128 * HHID + 255) / 256, 256>>>(Ws, p_ws, HHID);
    wconv_kernel<<<(128 * HHID + 255) / 256, 256>>>(Wt, p_wt, HHID);
    wconv_kernel<<<(128 * EMBED + 255) / 256, 256>>>(Wm, p_wm, EMBED);
    {
        dim3 g((N + 127) / 128, HHID / 128);
        tc_gemm_kernel<<<g, 256, TCG_SMEM_BYTES>>>(src_f, p_ws, bs, p_hs, N, HHID);
    }
    {
        dim3 g((M + 127) / 128, HHID / 128);
        tc_gemm_kernel<<<g, 256, TCG_SMEM_BYTES>>>(tgt_f, p_wt, bt, p_ht, M, HHID);
    }
    {
        dim3 g((N + 127) / 128, 1);
        tc_gemm_kernel<<<g, 256, TCG_SMEM_BYTES>>>(src_f, p_wm, bm, p_ms, N, EMBED);
    }
    hist_kernel<<<(E + 255) / 256, 256>>>(etgt, p_counts, E);
    scan_kernel<<<1, 1024>>>(p_counts, p_offsets, M);
    scatter_kernel<<<(E + 255) / 256, 256>>>(etgt, esrc, p_offsets, p_cursor, p_ssrc, E);
    {
        // one warp per (target, head): M*4 warps
        int warps = M * 4;
        int blocks = (warps + 7) / 8;
        edge_attn_kernel<<<blocks, 256>>>(p_ssrc, p_offsets,
                                          (const float4*)p_hs, (const float4*)p_ht,
                                          p_ms, (const float4*)aw,
                                          p_agg, M);
    }
    wconv_kernel<<<(128 * EMBED + 255) / 256, 256>>>(Wo, p_wo, EMBED);
    {
        dim3 g((M + 127) / 128, 1);
        tc_gemm_kernel<<<g, 256, TCG_SMEM_BYTES>>>(p_agg, p_wo, bo, out, M, EMBED);
    }
}

// round 10
// speedup vs baseline: 1.2740x; 1.0914x over previous
#include <cuda_runtime.h>
#include <cuda_bf16.h>
#include <math.h>
#include <stdint.h>

// Problem constants
#define EMBED 128
#define HHID  512
#define MAXN  50000
#define MAXM  50000
#define MAXE  400000

// ---------------------------------------------------------------------------
// Scratch
// ---------------------------------------------------------------------------
__device__ __align__(16) float g_hs[MAXN * HHID];
__device__ __align__(16) float g_ht[MAXM * HHID];
__device__ __align__(16) float g_ms[MAXN * EMBED];
__device__ __align__(16) float g_agg[MAXM * EMBED];
__device__ int g_counts[MAXM];
__device__ int g_cursor[MAXM];
__device__ int g_offsets[MAXM + 1];
__device__ int g_sorted_src[MAXE];
// weight tile images (pre-transposed n-major bf16 hi/lo per 128-col block)
__device__ __align__(16) __nv_bfloat16 g_wimg_src[5 * 32768];  // Ws (4 blocks) + Wm (1 block)
__device__ __align__(16) __nv_bfloat16 g_wimg_t[4 * 32768];    // Wt
__device__ __align__(16) __nv_bfloat16 g_wimg_o[32768];        // Wo

// ---------------------------------------------------------------------------
// helpers
// ---------------------------------------------------------------------------
__device__ __forceinline__ uint32_t smem_u32(const void* p) {
    uint32_t a;
    asm("{ .reg .u64 t; cvta.to.shared.u64 t, %1; cvt.u32.u64 %0, t; }" : "=r"(a) : "l"(p));
    return a;
}

__device__ __forceinline__ void ldsm_x4(uint32_t& r0, uint32_t& r1, uint32_t& r2, uint32_t& r3,
                                        uint32_t addr) {
    asm volatile("ldmatrix.sync.aligned.m8n8.x4.shared.b16 {%0,%1,%2,%3}, [%4];"
                 : "=r"(r0), "=r"(r1), "=r"(r2), "=r"(r3) : "r"(addr));
}

__device__ __forceinline__ void mma_bf16(float* d, const uint32_t* a, uint32_t b0, uint32_t b1) {
    asm volatile("mma.sync.aligned.m16n8k16.row.col.f32.bf16.bf16.f32 "
                 "{%0,%1,%2,%3}, {%4,%5,%6,%7}, {%8,%9}, {%0,%1,%2,%3};"
                 : "+f"(d[0]), "+f"(d[1]), "+f"(d[2]), "+f"(d[3])
                 : "r"(a[0]), "r"(a[1]), "r"(a[2]), "r"(a[3]), "r"(b0), "r"(b1));
}

// Branchless exact-GELU: erf via Abramowitz-Stegun 7.1.26 (|err| <= 1.5e-7)
__device__ __forceinline__ float gelu_fast(float x) {
    float z  = 0.70710678118654752440f * x;
    float az = fabsf(z);
    float t  = __fdividef(1.0f, fmaf(0.3275911f, az, 1.0f));
    float w  = fmaf(1.061405429f, t, -1.453152027f);
    w = fmaf(w, t, 1.421413741f);
    w = fmaf(w, t, -0.284496736f);
    w = fmaf(w, t, 0.254829592f);
    w = w * t;
    float e = __expf(-az * az);
    float erf_az = fmaf(-w, e, 1.0f);
    float erf_z  = copysignf(erf_az, z);
    return 0.5f * x * (1.0f + erf_z);
}

// ---------------------------------------------------------------------------
// weight conversion (all four weights, one launch)
// ---------------------------------------------------------------------------
__device__ __forceinline__ void wconv_one(const float* __restrict__ W, int idx, int ncols,
                                          __nv_bfloat16* __restrict__ imgbase) {
    int k = idx / ncols, c = idx - k * ncols;
    int nb = c >> 7, n = c & 127;
    float x = W[idx];
    __nv_bfloat16 h = __float2bfloat16(x);
    __nv_bfloat16 l = __float2bfloat16(x - __bfloat162float(h));
    __nv_bfloat16* base = imgbase + (size_t)nb * 32768;
    base[n * 128 + k] = h;
    base[16384 + n * 128 + k] = l;
}

__global__ void wconv4_kernel(const float* __restrict__ Ws, const float* __restrict__ Wm,
                              const float* __restrict__ Wt, const float* __restrict__ Wo,
                              __nv_bfloat16* __restrict__ img_src,
                              __nv_bfloat16* __restrict__ img_t,
                              __nv_bfloat16* __restrict__ img_o) {
    int i = blockIdx.x * 256 + threadIdx.x;
    if (i < 65536) {
        wconv_one(Ws, i, 512, img_src);
    } else if (i < 81920) {
        wconv_one(Wm, i - 65536, 128, img_src + 4 * 32768);
    } else if (i < 147456) {
        wconv_one(Wt, i - 81920, 512, img_t);
    } else if (i < 163840) {
        wconv_one(Wo, i - 147456, 128, img_o);
    }
}

// ---------------------------------------------------------------------------
// HMMA GEMM (dual-output): y-blocks [0,nyc1) -> C1/bias1/ncols1,
// y-blocks [nyc1,..) -> C2/bias2/ncols2. A is shared (one convert per CTA).
// bf16x3 split, fp32 accumulate. 128x128 tile, 256 threads, warp tile 32x64.
// ---------------------------------------------------------------------------
#define SMS 136
#define SM_TILE (128 * SMS)
#define TCG_SMEM_BYTES (4 * SM_TILE * 2)

__global__ void __launch_bounds__(256, 1)
tc_gemm_kernel(const float* __restrict__ A, const __nv_bfloat16* __restrict__ Bimg,
               const float* __restrict__ bias1, float* __restrict__ C1, int ncols1, int nyc1,
               const float* __restrict__ bias2, float* __restrict__ C2, int ncols2,
               int rows) {
    extern __shared__ __align__(16) __nv_bfloat16 sm[];
    __nv_bfloat16* sAh = sm;
    __nv_bfloat16* sAl = sm + SM_TILE;
    __nv_bfloat16* sBh = sm + 2 * SM_TILE;
    __nv_bfloat16* sBl = sm + 3 * SM_TILE;

    int tid = threadIdx.x, wid = tid >> 5, lane = tid & 31;
    int row0 = blockIdx.x * 128;
    int yb = blockIdx.y;
    const float* bias; float* C; int ncols, col0;
    if (yb < nyc1) { bias = bias1; C = C1; ncols = ncols1; col0 = yb * 128; }
    else           { bias = bias2; C = C2; ncols = ncols2; col0 = (yb - nyc1) * 128; }

    {
        const uint4* src = (const uint4*)(Bimg + (size_t)yb * 32768);
        for (int idx = tid; idx < 2048; idx += 256) {
            int n = idx >> 4, k8 = (idx & 15);
            uint4 vh = src[idx];
            uint4 vl = src[2048 + idx];
            *(uint4*)(sBh + n * SMS + k8 * 8) = vh;
            *(uint4*)(sBl + n * SMS + k8 * 8) = vl;
        }
    }
    for (int idx = tid; idx < 4096; idx += 256) {
        int r = idx >> 5, k0 = (idx & 31) * 4;
        float4 v = make_float4(0.f, 0.f, 0.f, 0.f);
        int gr = row0 + r;
        if (gr < rows) v = *(const float4*)(A + (size_t)gr * 128 + k0);
        uint32_t h01, h23;
        asm("cvt.rn.satfinite.bf16x2.f32 %0, %1, %2;" : "=r"(h01) : "f"(v.y), "f"(v.x));
        asm("cvt.rn.satfinite.bf16x2.f32 %0, %1, %2;" : "=r"(h23) : "f"(v.w), "f"(v.z));
        float r0f = v.x - __uint_as_float(h01 << 16);
        float r1f = v.y - __uint_as_float(h01 & 0xffff0000u);
        float r2f = v.z - __uint_as_float(h23 << 16);
        float r3f = v.w - __uint_as_float(h23 & 0xffff0000u);
        uint32_t l01, l23;
        asm("cvt.rn.satfinite.bf16x2.f32 %0, %1, %2;" : "=r"(l01) : "f"(r1f), "f"(r0f));
        asm("cvt.rn.satfinite.bf16x2.f32 %0, %1, %2;" : "=r"(l23) : "f"(r3f), "f"(r2f));
        *(uint2*)(sAh + r * SMS + k0) = make_uint2(h01, h23);
        *(uint2*)(sAl + r * SMS + k0) = make_uint2(l01, l23);
    }
    __syncthreads();

    int wm = (wid & 3) * 32;
    int wn = (wid >> 2) * 64;

    float acc[2][8][4];
    #pragma unroll
    for (int i = 0; i < 2; i++)
        #pragma unroll
        for (int j = 0; j < 8; j++)
            #pragma unroll
            for (int q = 0; q < 4; q++) acc[i][j][q] = 0.f;

    uint32_t a_base_h = smem_u32(sAh) + (((wm + (lane & 15)) * SMS + ((lane >> 4) << 3)) << 1);
    uint32_t a_base_l = a_base_h + (uint32_t)(SM_TILE << 1);
    uint32_t b_row = (uint32_t)(wn + ((lane & 16) >> 1) + (lane & 7));
    uint32_t b_base_h = smem_u32(sBh) + ((b_row * SMS + (lane & 8)) << 1);
    uint32_t b_base_l = b_base_h + (uint32_t)(SM_TILE << 1);

    #pragma unroll
    for (int ks = 0; ks < 8; ks++) {
        uint32_t koff = (uint32_t)(ks * 16 * 2);
        uint32_t ah[2][4], al[2][4];
        #pragma unroll
        for (int mt = 0; mt < 2; mt++) {
            uint32_t off = koff + (uint32_t)((mt * 16 * SMS) << 1);
            ldsm_x4(ah[mt][0], ah[mt][1], ah[mt][2], ah[mt][3], a_base_h + off);
            ldsm_x4(al[mt][0], al[mt][1], al[mt][2], al[mt][3], a_base_l + off);
        }
        #pragma unroll
        for (int np = 0; np < 4; np++) {
            uint32_t off = koff + (uint32_t)((np * 16 * SMS) << 1);
            uint32_t bh[4], bl[4];
            ldsm_x4(bh[0], bh[1], bh[2], bh[3], b_base_h + off);
            ldsm_x4(bl[0], bl[1], bl[2], bl[3], b_base_l + off);
            #pragma unroll
            for (int mt = 0; mt < 2; mt++) {
                mma_bf16(acc[mt][np * 2 + 0], ah[mt], bh[0], bh[1]);
                mma_bf16(acc[mt][np * 2 + 1], ah[mt], bh[2], bh[3]);
                mma_bf16(acc[mt][np * 2 + 0], ah[mt], bl[0], bl[1]);
                mma_bf16(acc[mt][np * 2 + 1], ah[mt], bl[2], bl[3]);
                mma_bf16(acc[mt][np * 2 + 0], al[mt], bh[0], bh[1]);
                mma_bf16(acc[mt][np * 2 + 1], al[mt], bh[2], bh[3]);
            }
        }
    }

    int g = lane >> 2, tg = lane & 3;
    #pragma unroll
    for (int mt = 0; mt < 2; mt++) {
        int r_lo = row0 + wm + mt * 16 + g;
        int r_hi = r_lo + 8;
        #pragma unroll
        for (int nt = 0; nt < 8; nt++) {
            int gc = col0 + wn + nt * 8 + tg * 2;
            float b0 = bias[gc], b1 = bias[gc + 1];
            if (r_lo < rows) {
                float2 o = make_float2(acc[mt][nt][0] + b0, acc[mt][nt][1] + b1);
                *(float2*)(C + (size_t)r_lo * ncols + gc) = o;
            }
            if (r_hi < rows) {
                float2 o = make_float2(acc[mt][nt][2] + b0, acc[mt][nt][3] + b1);
                *(float2*)(C + (size_t)r_hi * ncols + gc) = o;
            }
        }
    }
}

// ---------------------------------------------------------------------------
// CSR build
// ---------------------------------------------------------------------------
__global__ void zero2_kernel(int* a, int* b, int n) {
    int i = blockIdx.x * blockDim.x + threadIdx.x;
    if (i < n) { a[i] = 0; b[i] = 0; }
}
__global__ void hist_kernel(const int* __restrict__ etgt, int* __restrict__ counts, int E) {
    int i = blockIdx.x * blockDim.x + threadIdx.x;
    if (i < E) atomicAdd(&counts[etgt[i]], 1);
}
__global__ void scan_kernel(const int* __restrict__ counts, int* __restrict__ offsets, int M) {
    __shared__ int wsum[32];
    int t = threadIdx.x;
    int chunk = (M + 1023) >> 10;
    int b0 = t * chunk, b1 = b0 + chunk;
    if (b0 > M) b0 = M;
    if (b1 > M) b1 = M;
    int s = 0;
    for (int i = b0; i < b1; i++) s += counts[i];
    int lane = t & 31, w = t >> 5;
    int v = s;
    #pragma unroll
    for (int o = 1; o < 32; o <<= 1) { int x = __shfl_up_sync(0xffffffffu, v, o); if (lane >= o) v += x; }
    if (lane == 31) wsum[w] = v;
    __syncthreads();
    if (w == 0) {
        int x = wsum[lane];
        #pragma unroll
        for (int o = 1; o < 32; o <<= 1) { int y = __shfl_up_sync(0xffffffffu, x, o); if (lane >= o) x += y; }
        wsum[lane] = x;
    }
    __syncthreads();
    int run = v - s + (w > 0 ? wsum[w - 1] : 0);
    for (int i = b0; i < b1; i++) { offsets[i] = run; run += counts[i]; }
    if (t == 1023) offsets[M] = run;
}
__global__ void scatter_kernel(const int* __restrict__ etgt, const int* __restrict__ esrc,
                               const int* __restrict__ offsets, int* __restrict__ cursor,
                               int* __restrict__ ssrc, int E) {
    int i = blockIdx.x * blockDim.x + threadIdx.x;
    if (i < E) {
        int tg = etgt[i];
        int pos = offsets[tg] + atomicAdd(&cursor[tg], 1);
        ssrc[pos] = esrc[i];
    }
}

// ---------------------------------------------------------------------------
// Edge attention, head-split + 2-edge ILP. One warp per (target, head).
// The long chain (gather -> gelu -> dot -> butterfly) runs for 2 edges in
// parallel; only the cheap online-softmax update is sequential.
// ---------------------------------------------------------------------------
__global__ void __launch_bounds__(256)
edge_attn_kernel(const int* __restrict__ sorted_src,
                 const int* __restrict__ offsets,
                 const float4* __restrict__ hs4,
                 const float4* __restrict__ ht4,
                 const float* __restrict__ ms,
                 const float4* __restrict__ aw4,
                 float* __restrict__ agg,
                 int M) {
    int gw = (blockIdx.x * blockDim.x + threadIdx.x) >> 5;
    int lane = threadIdx.x & 31;
    int tgt = gw >> 2;
    int h = gw & 3;
    if (tgt >= M) return;
    int beg = offsets[tgt], end = offsets[tgt + 1];

    int fidx = h * 32 + lane;
    float4 htv = ht4[(size_t)tgt * 128 + fidx];
    float4 aw = aw4[fidx];

    float m = -3.4e38f;
    float d = 0.f;
    float acc = 0.f;

    int p = beg;
    for (; p + 1 < end; p += 2) {
        int s0 = sorted_src[p];
        int s1 = sorted_src[p + 1];
        float msg0 = ms[(size_t)s0 * 128 + fidx];
        float msg1 = ms[(size_t)s1 * 128 + fidx];
        float4 h0 = hs4[(size_t)s0 * 128 + fidx];
        float4 h1 = hs4[(size_t)s1 * 128 + fidx];

        float a0 = gelu_fast(h0.x + htv.x), b0 = gelu_fast(h0.y + htv.y);
        float c0 = gelu_fast(h0.z + htv.z), e0 = gelu_fast(h0.w + htv.w);
        float a1 = gelu_fast(h1.x + htv.x), b1 = gelu_fast(h1.y + htv.y);
        float c1 = gelu_fast(h1.z + htv.z), e1 = gelu_fast(h1.w + htv.w);
        float part0 = fmaf(a0, aw.x, fmaf(b0, aw.y, fmaf(c0, aw.z, e0 * aw.w)));
        float part1 = fmaf(a1, aw.x, fmaf(b1, aw.y, fmaf(c1, aw.z, e1 * aw.w)));
        #pragma unroll
        for (int o = 16; o > 0; o >>= 1) {
            part0 += __shfl_xor_sync(0xffffffffu, part0, o);
            part1 += __shfl_xor_sync(0xffffffffu, part1, o);
        }
        // sequential online updates (cheap)
        float nm = fmaxf(m, part0);
        float gm = __expf(m - nm);
        float ex = __expf(part0 - nm);
        d = fmaf(d, gm, ex);
        acc = fmaf(acc, gm, msg0 * ex);
        m = nm;
        nm = fmaxf(m, part1);
        gm = __expf(m - nm);
        ex = __expf(part1 - nm);
        d = fmaf(d, gm, ex);
        acc = fmaf(acc, gm, msg1 * ex);
        m = nm;
    }
    if (p < end) {
        int s0 = sorted_src[p];
        float msg0 = ms[(size_t)s0 * 128 + fidx];
        float4 h0 = hs4[(size_t)s0 * 128 + fidx];
        float a0 = gelu_fast(h0.x + htv.x), b0 = gelu_fast(h0.y + htv.y);
        float c0 = gelu_fast(h0.z + htv.z), e0 = gelu_fast(h0.w + htv.w);
        float part0 = fmaf(a0, aw.x, fmaf(b0, aw.y, fmaf(c0, aw.z, e0 * aw.w)));
        #pragma unroll
        for (int o = 16; o > 0; o >>= 1)
            part0 += __shfl_xor_sync(0xffffffffu, part0, o);
        float nm = fmaxf(m, part0);
        float gm = __expf(m - nm);
        float ex = __expf(part0 - nm);
        d = fmaf(d, gm, ex);
        acc = fmaf(acc, gm, msg0 * ex);
        m = nm;
    }

    float inv = (end > beg) ? (1.0f / d) : 0.0f;
    agg[(size_t)tgt * 128 + fidx] = acc * inv;
}

// ---------------------------------------------------------------------------
// launch
// ---------------------------------------------------------------------------
extern "C" void kernel_launch(void* const* d_in, const int* in_sizes, int n_in,
                              void* d_out, int out_size) {
    const float* src_f = (const float*)d_in[0];
    const float* tgt_f = (const float*)d_in[1];
    const int*   etgt  = (const int*)d_in[2];
    const int*   esrc  = (const int*)d_in[3];
    const float* Ws    = (const float*)d_in[4];
    const float* bs    = (const float*)d_in[5];
    const float* Wt    = (const float*)d_in[6];
    const float* bt    = (const float*)d_in[7];
    const float* aw    = (const float*)d_in[8];
    const float* Wm    = (const float*)d_in[9];
    const float* bm    = (const float*)d_in[10];
    const float* Wo    = (const float*)d_in[11];
    const float* bo    = (const float*)d_in[12];
    float* out = (float*)d_out;

    int N = in_sizes[0] / EMBED;
    int M = in_sizes[1] / EMBED;
    int E = in_sizes[2];

    float *p_hs, *p_ht, *p_ms, *p_agg;
    int *p_counts, *p_cursor, *p_offsets, *p_ssrc;
    __nv_bfloat16 *p_wsrc, *p_wt, *p_wo;
    cudaGetSymbolAddress((void**)&p_hs, g_hs);
    cudaGetSymbolAddress((void**)&p_ht, g_ht);
    cudaGetSymbolAddress((void**)&p_ms, g_ms);
    cudaGetSymbolAddress((void**)&p_agg, g_agg);
    cudaGetSymbolAddress((void**)&p_counts, g_counts);
    cudaGetSymbolAddress((void**)&p_cursor, g_cursor);
    cudaGetSymbolAddress((void**)&p_offsets, g_offsets);
    cudaGetSymbolAddress((void**)&p_ssrc, g_sorted_src);
    cudaGetSymbolAddress((void**)&p_wsrc, g_wimg_src);
    cudaGetSymbolAddress((void**)&p_wt, g_wimg_t);
    cudaGetSymbolAddress((void**)&p_wo, g_wimg_o);

    cudaFuncSetAttribute(tc_gemm_kernel,
                         cudaFuncAttributeMaxDynamicSharedMemorySize, TCG_SMEM_BYTES);

    zero2_kernel<<<(M + 255) / 256, 256>>>(p_counts, p_cursor, M);
    wconv4_kernel<<<640, 256>>>(Ws, Wm, Wt, Wo, p_wsrc, p_wt, p_wo);
    {
        // fused src GEMM: hs (4 y-blocks) + ms (1 y-block), one A-convert per CTA
        dim3 g((N + 127) / 128, 5);
        tc_gemm_kernel<<<g, 256, TCG_SMEM_BYTES>>>(src_f, p_wsrc,
                                                   bs, p_hs, HHID, 4,
                                                   bm, p_ms, EMBED, N);
    }
    {
        dim3 g((M + 127) / 128, 4);
        tc_gemm_kernel<<<g, 256, TCG_SMEM_BYTES>>>(tgt_f, p_wt,
                                                   bt, p_ht, HHID, 4,
                                                   bt, p_ht, HHID, M);
    }
    hist_kernel<<<(E + 255) / 256, 256>>>(etgt, p_counts, E);
    scan_kernel<<<1, 1024>>>(p_counts, p_offsets, M);
    scatter_kernel<<<(E + 255) / 256, 256>>>(etgt, esrc, p_offsets, p_cursor, p_ssrc, E);
    {
        int warps = M * 4;
        int blocks = (warps + 7) / 8;
        edge_attn_kernel<<<blocks, 256>>>(p_ssrc, p_offsets,
                                          (const float4*)p_hs, (const float4*)p_ht,
                                          p_ms, (const float4*)aw,
                                          p_agg, M);
    }
    {
        dim3 g((M + 127) / 128, 1);
        tc_gemm_kernel<<<g, 256, TCG_SMEM_BYTES>>>(p_agg, p_wo,
                                                   bo, out, EMBED, 1,
                                                   bo, out, EMBED, M);
    }
}

// round 13
// speedup vs baseline: 1.6577x; 1.3011x over previous
#include <cuda_runtime.h>
#include <cuda_bf16.h>
#include <math.h>
#include <stdint.h>

#define EMBED 128
#define HHID  512
#define MAXN  50000
#define MAXM  50000
#define MAXE  400000

// ---------------------------------------------------------------------------
// Scratch
// ---------------------------------------------------------------------------
__device__ __align__(16) float g_hs[MAXN * HHID];
__device__ __align__(16) float g_ht[MAXM * HHID];
__device__ __align__(16) float g_ms[MAXN * EMBED];
__device__ __align__(16) float g_agg[MAXM * EMBED];
__device__ int g_counts[MAXM];
__device__ int g_cursor[MAXM];
__device__ int g_offsets[MAXM + 1];
__device__ int g_sorted_src[MAXE];
__device__ __align__(16) __nv_bfloat16 g_wimg_src[5 * 32768];  // Ws (4 blocks) + Wm (1)
__device__ __align__(16) __nv_bfloat16 g_wimg_t[4 * 32768];    // Wt
__device__ __align__(16) __nv_bfloat16 g_wimg_o[32768];        // Wo

// ---------------------------------------------------------------------------
// helpers
// ---------------------------------------------------------------------------
__device__ __forceinline__ uint32_t smem_u32(const void* p) {
    uint32_t a;
    asm("{ .reg .u64 t; cvta.to.shared.u64 t, %1; cvt.u32.u64 %0, t; }" : "=r"(a) : "l"(p));
    return a;
}
__device__ __forceinline__ void ldsm_x4(uint32_t& r0, uint32_t& r1, uint32_t& r2, uint32_t& r3,
                                        uint32_t addr) {
    asm volatile("ldmatrix.sync.aligned.m8n8.x4.shared.b16 {%0,%1,%2,%3}, [%4];"
                 : "=r"(r0), "=r"(r1), "=r"(r2), "=r"(r3) : "r"(addr));
}
__device__ __forceinline__ void mma_bf16(float* d, const uint32_t* a, uint32_t b0, uint32_t b1) {
    asm volatile("mma.sync.aligned.m16n8k16.row.col.f32.bf16.bf16.f32 "
                 "{%0,%1,%2,%3}, {%4,%5,%6,%7}, {%8,%9}, {%0,%1,%2,%3};"
                 : "+f"(d[0]), "+f"(d[1]), "+f"(d[2]), "+f"(d[3])
                 : "r"(a[0]), "r"(a[1]), "r"(a[2]), "r"(a[3]), "r"(b0), "r"(b1));
}
__device__ __forceinline__ float gelu_fast(float x) {
    float z  = 0.70710678118654752440f * x;
    float az = fabsf(z);
    float t  = __fdividef(1.0f, fmaf(0.3275911f, az, 1.0f));
    float w  = fmaf(1.061405429f, t, -1.453152027f);
    w = fmaf(w, t, 1.421413741f);
    w = fmaf(w, t, -0.284496736f);
    w = fmaf(w, t, 0.254829592f);
    w = w * t;
    float e = __expf(-az * az);
    float erf_az = fmaf(-w, e, 1.0f);
    float erf_z  = copysignf(erf_az, z);
    return 0.5f * x * (1.0f + erf_z);
}

// ---------------------------------------------------------------------------
// weight conversion (all four weights, one launch)
// ---------------------------------------------------------------------------
__device__ __forceinline__ void wconv_one(const float* __restrict__ W, int idx, int ncols,
                                          __nv_bfloat16* __restrict__ imgbase) {
    int k = idx / ncols, c = idx - k * ncols;
    int nb = c >> 7, n = c & 127;
    float x = W[idx];
    __nv_bfloat16 h = __float2bfloat16(x);
    __nv_bfloat16 l = __float2bfloat16(x - __bfloat162float(h));
    __nv_bfloat16* base = imgbase + (size_t)nb * 32768;
    base[n * 128 + k] = h;
    base[16384 + n * 128 + k] = l;
}
__global__ void wconv4_kernel(const float* __restrict__ Ws, const float* __restrict__ Wm,
                              const float* __restrict__ Wt, const float* __restrict__ Wo,
                              __nv_bfloat16* __restrict__ img_src,
                              __nv_bfloat16* __restrict__ img_t,
                              __nv_bfloat16* __restrict__ img_o) {
    int i = blockIdx.x * 256 + threadIdx.x;
    if (i < 65536) {
        wconv_one(Ws, i, 512, img_src);
    } else if (i < 81920) {
        wconv_one(Wm, i - 65536, 128, img_src + 4 * 32768);
    } else if (i < 147456) {
        wconv_one(Wt, i - 81920, 512, img_t);
    } else if (i < 163840) {
        wconv_one(Wo, i - 147456, 128, img_o);
    }
}

// ---------------------------------------------------------------------------
// Persistent fused HMMA GEMM.
// Jobs (blockIdx.y + jobbase):
//   0-3: src @ Ws block j  -> hs cols j*128    (ncols 512)
//   4  : src @ Wm          -> ms               (ncols 128)
//   5-8: tgt @ Wt block j-5-> ht cols (j-5)*128(ncols 512)
//   9  : agg @ Wo          -> out              (ncols 128)
// Each CTA loads its B tile ONCE, then streams x-blocks with cp.async
// prefetch of raw A overlapping the MMA mainloop. bf16x3 split, fp32 acc.
// ---------------------------------------------------------------------------
#define SMS 136
#define SM_TILE (128 * SMS)                 // bf16 elements per tile image
#define RAW_BYTES 65536                     // 128x128 fp32 raw A tile
#define PERSIST_SMEM (RAW_BYTES + 4 * SM_TILE * 2)   // 204800 B

__device__ __forceinline__ void prefetch_a(const float* __restrict__ A, int row0, int rows,
                                           int tid, uint32_t sraw) {
    #pragma unroll
    for (int it = 0; it < 16; it++) {
        int idx = tid + it * 256;
        int r = idx >> 5, c4 = idx & 31;
        int gr = row0 + r;
        if (gr >= rows) gr = rows - 1;
        const float* src = A + (size_t)gr * 128 + c4 * 4;
        asm volatile("cp.async.ca.shared.global [%0], [%1], 16;"
                     :: "r"(sraw + (uint32_t)idx * 16), "l"(src));
    }
}

__global__ void __launch_bounds__(256, 1)
tc_gemm_persist(const float* __restrict__ Asrc, const float* __restrict__ Atgt,
                const float* __restrict__ Aagg,
                const __nv_bfloat16* __restrict__ img_src,
                const __nv_bfloat16* __restrict__ img_t,
                const __nv_bfloat16* __restrict__ img_o,
                const float* __restrict__ bs, const float* __restrict__ bm,
                const float* __restrict__ bt, const float* __restrict__ bo,
                float* __restrict__ hs, float* __restrict__ msp, float* __restrict__ ht,
                float* __restrict__ outp,
                int N, int M, int jobbase) {
    extern __shared__ __align__(16) char smraw[];
    float* sRawF = (float*)smraw;
    __nv_bfloat16* sAh = (__nv_bfloat16*)(smraw + RAW_BYTES);
    __nv_bfloat16* sAl = sAh + SM_TILE;
    __nv_bfloat16* sBh = sAl + SM_TILE;
    __nv_bfloat16* sBl = sBh + SM_TILE;

    int tid = threadIdx.x, wid = tid >> 5, lane = tid & 31;
    int job = jobbase + blockIdx.y;

    const float* A; const __nv_bfloat16* Bimg; const float* bias;
    float* C; int ncols, col0, rows;
    if (job < 4)      { A = Asrc; rows = N; Bimg = img_src + (size_t)job * 32768;
                        bias = bs; C = hs;  ncols = 512; col0 = job * 128; }
    else if (job == 4){ A = Asrc; rows = N; Bimg = img_src + 4ull * 32768;
                        bias = bm; C = msp; ncols = 128; col0 = 0; }
    else if (job < 9) { A = Atgt; rows = M; Bimg = img_t + (size_t)(job - 5) * 32768;
                        bias = bt; C = ht;  ncols = 512; col0 = (job - 5) * 128; }
    else              { A = Aagg; rows = M; Bimg = img_o;
                        bias = bo; C = outp; ncols = 128; col0 = 0; }

    int nxb = (rows + 127) >> 7;
    uint32_t sraw = smem_u32(sRawF);

    // ---- load B tile once ----
    {
        const uint4* src = (const uint4*)Bimg;
        for (int idx = tid; idx < 2048; idx += 256) {
            int n = idx >> 4, k8 = (idx & 15);
            uint4 vh = src[idx];
            uint4 vl = src[2048 + idx];
            *(uint4*)(sBh + n * SMS + k8 * 8) = vh;
            *(uint4*)(sBl + n * SMS + k8 * 8) = vl;
        }
    }

    // ---- prefetch first A tile ----
    int xb0 = blockIdx.x;
    if (xb0 < nxb) prefetch_a(A, xb0 << 7, rows, tid, sraw);
    asm volatile("cp.async.commit_group;" ::: "memory");
    __syncthreads();   // B visible

    int wm = (wid & 3) * 32;
    int wn = (wid >> 2) * 64;
    uint32_t a_base_h = smem_u32(sAh) + (((wm + (lane & 15)) * SMS + ((lane >> 4) << 3)) << 1);
    uint32_t a_base_l = a_base_h + (uint32_t)(SM_TILE << 1);
    uint32_t b_row = (uint32_t)(wn + ((lane & 16) >> 1) + (lane & 7));
    uint32_t b_base_h = smem_u32(sBh) + ((b_row * SMS + (lane & 8)) << 1);
    uint32_t b_base_l = b_base_h + (uint32_t)(SM_TILE << 1);

    for (int xb = xb0; xb < nxb; xb += gridDim.x) {
        int row0 = xb << 7;
        asm volatile("cp.async.wait_group 0;" ::: "memory");
        __syncthreads();     // raw ready, previous mainloop done

        // ---- convert raw -> bf16 hi/lo ----
        #pragma unroll
        for (int it = 0; it < 16; it++) {
            int idx = tid + it * 256;
            int r = idx >> 5, k0 = (idx & 31) * 4;
            float4 v = *(const float4*)(sRawF + idx * 4);
            uint32_t h01, h23;
            asm("cvt.rn.satfinite.bf16x2.f32 %0, %1, %2;" : "=r"(h01) : "f"(v.y), "f"(v.x));
            asm("cvt.rn.satfinite.bf16x2.f32 %0, %1, %2;" : "=r"(h23) : "f"(v.w), "f"(v.z));
            float r0f = v.x - __uint_as_float(h01 << 16);
            float r1f = v.y - __uint_as_float(h01 & 0xffff0000u);
            float r2f = v.z - __uint_as_float(h23 << 16);
            float r3f = v.w - __uint_as_float(h23 & 0xffff0000u);
            uint32_t l01, l23;
            asm("cvt.rn.satfinite.bf16x2.f32 %0, %1, %2;" : "=r"(l01) : "f"(r1f), "f"(r0f));
            asm("cvt.rn.satfinite.bf16x2.f32 %0, %1, %2;" : "=r"(l23) : "f"(r3f), "f"(r2f));
            *(uint2*)(sAh + r * SMS + k0) = make_uint2(h01, h23);
            *(uint2*)(sAl + r * SMS + k0) = make_uint2(l01, l23);
        }
        __syncthreads();     // converted A visible; raw free

        // ---- prefetch next A tile (overlaps mainloop) ----
        int xn = xb + gridDim.x;
        if (xn < nxb) prefetch_a(A, xn << 7, rows, tid, sraw);
        asm volatile("cp.async.commit_group;" ::: "memory");

        // ---- mainloop ----
        float acc[2][8][4];
        #pragma unroll
        for (int i = 0; i < 2; i++)
            #pragma unroll
            for (int j = 0; j < 8; j++)
                #pragma unroll
                for (int q = 0; q < 4; q++) acc[i][j][q] = 0.f;

        #pragma unroll
        for (int ks = 0; ks < 8; ks++) {
            uint32_t koff = (uint32_t)(ks * 16 * 2);
            uint32_t ah[2][4], al[2][4];
            #pragma unroll
            for (int mt = 0; mt < 2; mt++) {
                uint32_t off = koff + (uint32_t)((mt * 16 * SMS) << 1);
                ldsm_x4(ah[mt][0], ah[mt][1], ah[mt][2], ah[mt][3], a_base_h + off);
                ldsm_x4(al[mt][0], al[mt][1], al[mt][2], al[mt][3], a_base_l + off);
            }
            #pragma unroll
            for (int np = 0; np < 4; np++) {
                uint32_t off = koff + (uint32_t)((np * 16 * SMS) << 1);
                uint32_t bh[4], bl[4];
                ldsm_x4(bh[0], bh[1], bh[2], bh[3], b_base_h + off);
                ldsm_x4(bl[0], bl[1], bl[2], bl[3], b_base_l + off);
                #pragma unroll
                for (int mt = 0; mt < 2; mt++) {
                    mma_bf16(acc[mt][np * 2 + 0], ah[mt], bh[0], bh[1]);
                    mma_bf16(acc[mt][np * 2 + 1], ah[mt], bh[2], bh[3]);
                    mma_bf16(acc[mt][np * 2 + 0], ah[mt], bl[0], bl[1]);
                    mma_bf16(acc[mt][np * 2 + 1], ah[mt], bl[2], bl[3]);
                    mma_bf16(acc[mt][np * 2 + 0], al[mt], bh[0], bh[1]);
                    mma_bf16(acc[mt][np * 2 + 1], al[mt], bh[2], bh[3]);
                }
            }
        }

        // ---- epilogue ----
        int g = lane >> 2, tg = lane & 3;
        #pragma unroll
        for (int mt = 0; mt < 2; mt++) {
            int r_lo = row0 + wm + mt * 16 + g;
            int r_hi = r_lo + 8;
            #pragma unroll
            for (int nt = 0; nt < 8; nt++) {
                int gc = col0 + wn + nt * 8 + tg * 2;
                float b0 = bias[gc], b1 = bias[gc + 1];
                if (r_lo < rows) {
                    float2 o = make_float2(acc[mt][nt][0] + b0, acc[mt][nt][1] + b1);
                    *(float2*)(C + (size_t)r_lo * ncols + gc) = o;
                }
                if (r_hi < rows) {
                    float2 o = make_float2(acc[mt][nt][2] + b0, acc[mt][nt][3] + b1);
                    *(float2*)(C + (size_t)r_hi * ncols + gc) = o;
                }
            }
        }
    }
}

// ---------------------------------------------------------------------------
// CSR build
// ---------------------------------------------------------------------------
__global__ void zero2_kernel(int* a, int* b, int n) {
    int i = blockIdx.x * blockDim.x + threadIdx.x;
    if (i < n) { a[i] = 0; b[i] = 0; }
}
__global__ void hist_kernel(const int* __restrict__ etgt, int* __restrict__ counts, int E) {
    int i = blockIdx.x * blockDim.x + threadIdx.x;
    if (i < E) atomicAdd(&counts[etgt[i]], 1);
}
__global__ void scan_kernel(const int* __restrict__ counts, int* __restrict__ offsets, int M) {
    __shared__ int wsum[32];
    int t = threadIdx.x;
    int chunk = (M + 1023) >> 10;
    int b0 = t * chunk, b1 = b0 + chunk;
    if (b0 > M) b0 = M;
    if (b1 > M) b1 = M;
    int s = 0;
    for (int i = b0; i < b1; i++) s += counts[i];
    int lane = t & 31, w = t >> 5;
    int v = s;
    #pragma unroll
    for (int o = 1; o < 32; o <<= 1) { int x = __shfl_up_sync(0xffffffffu, v, o); if (lane >= o) v += x; }
    if (lane == 31) wsum[w] = v;
    __syncthreads();
    if (w == 0) {
        int x = wsum[lane];
        #pragma unroll
        for (int o = 1; o < 32; o <<= 1) { int y = __shfl_up_sync(0xffffffffu, x, o); if (lane >= o) x += y; }
        wsum[lane] = x;
    }
    __syncthreads();
    int run = v - s + (w > 0 ? wsum[w - 1] : 0);
    for (int i = b0; i < b1; i++) { offsets[i] = run; run += counts[i]; }
    if (t == 1023) offsets[M] = run;
}
__global__ void scatter_kernel(const int* __restrict__ etgt, const int* __restrict__ esrc,
                               const int* __restrict__ offsets, int* __restrict__ cursor,
                               int* __restrict__ ssrc, int E) {
    int i = blockIdx.x * blockDim.x + threadIdx.x;
    if (i < E) {
        int tg = etgt[i];
        int pos = offsets[tg] + atomicAdd(&cursor[tg], 1);
        ssrc[pos] = esrc[i];
    }
}

// ---------------------------------------------------------------------------
// Edge attention, head-split + 2-edge ILP (unchanged from R10)
// ---------------------------------------------------------------------------
__global__ void __launch_bounds__(256)
edge_attn_kernel(const int* __restrict__ sorted_src,
                 const int* __restrict__ offsets,
                 const float4* __restrict__ hs4,
                 const float4* __restrict__ ht4,
                 const float* __restrict__ ms,
                 const float4* __restrict__ aw4,
                 float* __restrict__ agg,
                 int M) {
    int gw = (blockIdx.x * blockDim.x + threadIdx.x) >> 5;
    int lane = threadIdx.x & 31;
    int tgt = gw >> 2;
    int h = gw & 3;
    if (tgt >= M) return;
    int beg = offsets[tgt], end = offsets[tgt + 1];

    int fidx = h * 32 + lane;
    float4 htv = ht4[(size_t)tgt * 128 + fidx];
    float4 aw = aw4[fidx];

    float m = -3.4e38f;
    float d = 0.f;
    float acc = 0.f;

    int p = beg;
    for (; p + 1 < end; p += 2) {
        int s0 = sorted_src[p];
        int s1 = sorted_src[p + 1];
        float msg0 = ms[(size_t)s0 * 128 + fidx];
        float msg1 = ms[(size_t)s1 * 128 + fidx];
        float4 h0 = hs4[(size_t)s0 * 128 + fidx];
        float4 h1 = hs4[(size_t)s1 * 128 + fidx];

        float a0 = gelu_fast(h0.x + htv.x), b0 = gelu_fast(h0.y + htv.y);
        float c0 = gelu_fast(h0.z + htv.z), e0 = gelu_fast(h0.w + htv.w);
        float a1 = gelu_fast(h1.x + htv.x), b1 = gelu_fast(h1.y + htv.y);
        float c1 = gelu_fast(h1.z + htv.z), e1 = gelu_fast(h1.w + htv.w);
        float part0 = fmaf(a0, aw.x, fmaf(b0, aw.y, fmaf(c0, aw.z, e0 * aw.w)));
        float part1 = fmaf(a1, aw.x, fmaf(b1, aw.y, fmaf(c1, aw.z, e1 * aw.w)));
        #pragma unroll
        for (int o = 16; o > 0; o >>= 1) {
            part0 += __shfl_xor_sync(0xffffffffu, part0, o);
            part1 += __shfl_xor_sync(0xffffffffu, part1, o);
        }
        float nm = fmaxf(m, part0);
        float gm = __expf(m - nm);
        float ex = __expf(part0 - nm);
        d = fmaf(d, gm, ex);
        acc = fmaf(acc, gm, msg0 * ex);
        m = nm;
        nm = fmaxf(m, part1);
        gm = __expf(m - nm);
        ex = __expf(part1 - nm);
        d = fmaf(d, gm, ex);
        acc = fmaf(acc, gm, msg1 * ex);
        m = nm;
    }
    if (p < end) {
        int s0 = sorted_src[p];
        float msg0 = ms[(size_t)s0 * 128 + fidx];
        float4 h0 = hs4[(size_t)s0 * 128 + fidx];
        float a0 = gelu_fast(h0.x + htv.x), b0 = gelu_fast(h0.y + htv.y);
        float c0 = gelu_fast(h0.z + htv.z), e0 = gelu_fast(h0.w + htv.w);
        float part0 = fmaf(a0, aw.x, fmaf(b0, aw.y, fmaf(c0, aw.z, e0 * aw.w)));
        #pragma unroll
        for (int o = 16; o > 0; o >>= 1)
            part0 += __shfl_xor_sync(0xffffffffu, part0, o);
        float nm = fmaxf(m, part0);
        float gm = __expf(m - nm);
        float ex = __expf(part0 - nm);
        d = fmaf(d, gm, ex);
        acc = fmaf(acc, gm, msg0 * ex);
        m = nm;
    }

    float inv = (end > beg) ? (1.0f / d) : 0.0f;
    agg[(size_t)tgt * 128 + fidx] = acc * inv;
}

// ---------------------------------------------------------------------------
// launch
// ---------------------------------------------------------------------------
extern "C" void kernel_launch(void* const* d_in, const int* in_sizes, int n_in,
                              void* d_out, int out_size) {
    const float* src_f = (const float*)d_in[0];
    const float* tgt_f = (const float*)d_in[1];
    const int*   etgt  = (const int*)d_in[2];
    const int*   esrc  = (const int*)d_in[3];
    const float* Ws    = (const float*)d_in[4];
    const float* bs    = (const float*)d_in[5];
    const float* Wt    = (const float*)d_in[6];
    const float* bt    = (const float*)d_in[7];
    const float* aw    = (const float*)d_in[8];
    const float* Wm    = (const float*)d_in[9];
    const float* bm    = (const float*)d_in[10];
    const float* Wo    = (const float*)d_in[11];
    const float* bo    = (const float*)d_in[12];
    float* out = (float*)d_out;

    int N = in_sizes[0] / EMBED;
    int M = in_sizes[1] / EMBED;
    int E = in_sizes[2];

    float *p_hs, *p_ht, *p_ms, *p_agg;
    int *p_counts, *p_cursor, *p_offsets, *p_ssrc;
    __nv_bfloat16 *p_wsrc, *p_wt, *p_wo;
    cudaGetSymbolAddress((void**)&p_hs, g_hs);
    cudaGetSymbolAddress((void**)&p_ht, g_ht);
    cudaGetSymbolAddress((void**)&p_ms, g_ms);
    cudaGetSymbolAddress((void**)&p_agg, g_agg);
    cudaGetSymbolAddress((void**)&p_counts, g_counts);
    cudaGetSymbolAddress((void**)&p_cursor, g_cursor);
    cudaGetSymbolAddress((void**)&p_offsets, g_offsets);
    cudaGetSymbolAddress((void**)&p_ssrc, g_sorted_src);
    cudaGetSymbolAddress((void**)&p_wsrc, g_wimg_src);
    cudaGetSymbolAddress((void**)&p_wt, g_wimg_t);
    cudaGetSymbolAddress((void**)&p_wo, g_wimg_o);

    cudaFuncSetAttribute(tc_gemm_persist,
                         cudaFuncAttributeMaxDynamicSharedMemorySize, PERSIST_SMEM);

    // order: CSR first, so launch #5 (ncu capture slot) is the fused GEMM
    zero2_kernel<<<(M + 255) / 256, 256>>>(p_counts, p_cursor, M);                        // 0
    hist_kernel<<<(E + 255) / 256, 256>>>(etgt, p_counts, E);                             // 1
    scan_kernel<<<1, 1024>>>(p_counts, p_offsets, M);                                     // 2
    scatter_kernel<<<(E + 255) / 256, 256>>>(etgt, esrc, p_offsets, p_cursor, p_ssrc, E); // 3
    wconv4_kernel<<<640, 256>>>(Ws, Wm, Wt, Wo, p_wsrc, p_wt, p_wo);                      // 4
    {
        dim3 g(16, 9);                                                                    // 5 (captured)
        tc_gemm_persist<<<g, 256, PERSIST_SMEM>>>(src_f, tgt_f, p_agg,
                                                  p_wsrc, p_wt, p_wo,
                                                  bs, bm, bt, bo,
                                                  p_hs, p_ms, p_ht, out,
                                                  N, M, 0);
    }
    {
        int warps = M * 4;                                                                // 6
        int blocks = (warps + 7) / 8;
        edge_attn_kernel<<<blocks, 256>>>(p_ssrc, p_offsets,
                                          (const float4*)p_hs, (const float4*)p_ht,
                                          p_ms, (const float4*)aw,
                                          p_agg, M);
    }
    {
        dim3 g(148, 1);                                                                   // 7
        tc_gemm_persist<<<g, 256, PERSIST_SMEM>>>(src_f, tgt_f, p_agg,
                                                  p_wsrc, p_wt, p_wo,
                                                  bs, bm, bt, bo,
                                                  p_hs, p_ms, p_ht, out,
                                                  N, M, 9);
    }
}